// round 5
// baseline (speedup 1.0000x reference)
#include <cuda_runtime.h>
#include <cuda_fp16.h>
#include <cuda_bf16.h>

#define NN 4
#define NQ 256
#define NV 512
#define NE 256

// Scratch (allocation-free requirement)
__device__ float g_logits[NN * NQ * NV];     // raw logits (2 MB)
__device__ float g_pvp[8][NN * NQ * NE];     // split-K partials of exp(l)@memory (8 MB)
__device__ float g_den[8][NN * NQ];          // split-K partials of sum_v exp(l)
__device__ float g_heads[NN * NQ * NE];      // merged, normalized, leaky heads (1 MB)

// ---------------------------------------------------------------------------
// helpers
// ---------------------------------------------------------------------------
__device__ __forceinline__ uint4 pack8(const float4 a, const float4 b) {
    __half2 h0 = __floats2half2_rn(a.x, a.y);
    __half2 h1 = __floats2half2_rn(a.z, a.w);
    __half2 h2 = __floats2half2_rn(b.x, b.y);
    __half2 h3 = __floats2half2_rn(b.z, b.w);
    uint4 r;
    r.x = *reinterpret_cast<unsigned*>(&h0);
    r.y = *reinterpret_cast<unsigned*>(&h1);
    r.z = *reinterpret_cast<unsigned*>(&h2);
    r.w = *reinterpret_cast<unsigned*>(&h3);
    return r;
}

__device__ __forceinline__ __half2 u2h(unsigned u) {
    return *reinterpret_cast<__half2*>(&u);
}

// tanh of (q+c) in f16x2, times w (f16x2)
__device__ __forceinline__ __half2 wtanh(unsigned cv, unsigned qv, unsigned wv) {
    __half2 s = __hadd2(u2h(qv), u2h(cv));
    unsigned su = *reinterpret_cast<unsigned*>(&s);
    unsigned tu;
    asm("tanh.approx.f16x2 %0, %1;" : "=r"(tu) : "r"(su));
    return __hmul2(u2h(tu), u2h(wv));
}

// packed f32x2 FMA
__device__ __forceinline__ unsigned long long splat2(float x) {
    unsigned long long r;
    asm("mov.b64 %0, {%1, %1};" : "=l"(r) : "r"(__float_as_uint(x)));
    return r;
}
__device__ __forceinline__ void ffma2(unsigned long long& d,
                                      unsigned long long a, unsigned long long b) {
    asm("fma.rn.f32x2 %0, %1, %2, %0;" : "+l"(d) : "l"(a), "l"(b));
}

// ---------------------------------------------------------------------------
// K1: logits[n,q,v] = sum_e w[e]*tanh(q+c) + b.
// Warp = q-row, lane = v. Octet pipeline: HADD2 -> MUFU tanh f16x2 -> HMUL2
// -> HADD2 tree -> one h2->f32 convert per octet, fp32 accumulate.
// ct row stride 33 uint4 (== 4 mod 32 words): conflict-free LDS.128 & STS.128.
// ---------------------------------------------------------------------------
__global__ void __launch_bounds__(256) k_logits(
    const float* __restrict__ q, const float* __restrict__ c,
    const float* __restrict__ wl, const float* __restrict__ bl_p)
{
    __shared__ uint4 ct[32][33];    // 16.9 KB, [e-octet][v]
    __shared__ uint4 qs[8][32];     // 4 KB,    [q-row][e-octet]
    __shared__ uint4 ws[32];        // 512 B,   w as f16 octets

    const int n = blockIdx.z;
    const int qbase = blockIdx.x * 8;
    const int tid = threadIdx.x;
    const int wq = tid >> 5, lane = tid & 31;

    {   // one q-octet per thread
        int r = tid >> 5, g = tid & 31;
        const float4* src =
            (const float4*)&q[((size_t)n * NQ + qbase + r) * NE + g * 8];
        qs[r][g] = pack8(src[0], src[1]);
    }
    if (tid < 32) {
        const float4* src = (const float4*)&wl[tid * 8];
        ws[tid] = pack8(src[0], src[1]);
    }
    const float bl = __ldg(bl_p);

    #pragma unroll
    for (int t = 0; t < 2; ++t) {
        __syncthreads();
        const int vbase = blockIdx.y * 64 + t * 32;
        for (int i = tid; i < 1024; i += 256) {   // 32 v x 32 octets
            int v = i >> 5, g = i & 31;
            const float4* src =
                (const float4*)&c[((size_t)n * NV + vbase + v) * NE + g * 8];
            ct[g][v] = pack8(src[0], src[1]);
        }
        __syncthreads();

        float a0 = 0.f, a1 = 0.f;
        #pragma unroll 8
        for (int g = 0; g < 32; ++g) {
            uint4 cb = ct[g][lane];
            uint4 qb = qs[wq][g];
            uint4 wb = ws[g];
            __half2 p0 = wtanh(cb.x, qb.x, wb.x);
            __half2 p1 = wtanh(cb.y, qb.y, wb.y);
            __half2 p2 = wtanh(cb.z, qb.z, wb.z);
            __half2 p3 = wtanh(cb.w, qb.w, wb.w);
            __half2 ps = __hadd2(__hadd2(p0, p1), __hadd2(p2, p3));
            float2 f = __half22float2(ps);
            a0 += f.x;
            a1 += f.y;
        }
        g_logits[((size_t)n * NQ + qbase + wq) * NV + vbase + lane] =
            a0 + a1 + bl;
    }
}

// ---------------------------------------------------------------------------
// K2: split-K(8x64) of exp(l/t) @ memory; exp during A-staging (logits
// bounded, no max-shift). Emits per-row denominator partials.
// ---------------------------------------------------------------------------
__global__ void __launch_bounds__(256) k_pv(
    const float* __restrict__ Mm, const float* __restrict__ temp_p)
{
    const int n = blockIdx.z >> 3, s = blockIdx.z & 7;
    const int m0 = blockIdx.y * 64, n0 = blockIdx.x * 64;
    const float* A = g_logits + (size_t)n * NQ * NV;
    const float* B = Mm + (size_t)n * NV * NE;
    const float invt = 1.0f / __ldg(temp_p);

    __shared__ float As[32][68];
    __shared__ float Bs[32][68];

    const int tid = threadIdx.x;
    const int tx = tid & 15, ty = tid >> 4;
    const int ar = tid >> 2, ac = (tid & 3) * 8;
    const int bkr = tid >> 3, bc = (tid & 7) * 8;

    unsigned long long acc[4][2] = {};
    float dsum = 0.f;

    #pragma unroll
    for (int it = 0; it < 2; ++it) {
        const int k0 = s * 64 + it * 32;
        float4 l0 = *(const float4*)&A[(size_t)(m0 + ar) * NV + k0 + ac];
        float4 l1 = *(const float4*)&A[(size_t)(m0 + ar) * NV + k0 + ac + 4];
        float e0 = __expf(l0.x * invt), e1 = __expf(l0.y * invt);
        float e2 = __expf(l0.z * invt), e3 = __expf(l0.w * invt);
        float e4 = __expf(l1.x * invt), e5 = __expf(l1.y * invt);
        float e6 = __expf(l1.z * invt), e7 = __expf(l1.w * invt);
        As[ac + 0][ar] = e0; As[ac + 1][ar] = e1;
        As[ac + 2][ar] = e2; As[ac + 3][ar] = e3;
        As[ac + 4][ar] = e4; As[ac + 5][ar] = e5;
        As[ac + 6][ar] = e6; As[ac + 7][ar] = e7;
        dsum += ((e0 + e1) + (e2 + e3)) + ((e4 + e5) + (e6 + e7));
        *(float4*)&Bs[bkr][bc] =
            *(const float4*)&B[(size_t)(k0 + bkr) * NE + n0 + bc];
        *(float4*)&Bs[bkr][bc + 4] =
            *(const float4*)&B[(size_t)(k0 + bkr) * NE + n0 + bc + 4];
        __syncthreads();
        #pragma unroll
        for (int k = 0; k < 32; ++k) {
            float4 av = *(const float4*)&As[k][ty * 4];
            ulonglong2 bv = *(const ulonglong2*)&Bs[k][tx * 4];
            ffma2(acc[0][0], splat2(av.x), bv.x); ffma2(acc[0][1], splat2(av.x), bv.y);
            ffma2(acc[1][0], splat2(av.y), bv.x); ffma2(acc[1][1], splat2(av.y), bv.y);
            ffma2(acc[2][0], splat2(av.z), bv.x); ffma2(acc[2][1], splat2(av.z), bv.y);
            ffma2(acc[3][0], splat2(av.w), bv.x); ffma2(acc[3][1], splat2(av.w), bv.y);
        }
        __syncthreads();
    }

    // denominator partial: 4 staging threads share row ar
    dsum += __shfl_xor_sync(0xffffffffu, dsum, 1);
    dsum += __shfl_xor_sync(0xffffffffu, dsum, 2);
    if (blockIdx.x == 0 && (tid & 3) == 0)
        g_den[s][n * NQ + m0 + ar] = dsum;

    float* P = g_pvp[s] + (size_t)n * NQ * NE;
    #pragma unroll
    for (int i = 0; i < 4; ++i) {
        float2 lo = *reinterpret_cast<float2*>(&acc[i][0]);
        float2 hi = *reinterpret_cast<float2*>(&acc[i][1]);
        *(float4*)&P[(size_t)(m0 + ty * 4 + i) * NE + n0 + tx * 4] =
            make_float4(lo.x, lo.y, hi.x, hi.y);
    }
}

// ---------------------------------------------------------------------------
// K3: merge split-K partials -> heads = leaky( sum_s pvp / sum_s den )
// One float4 per thread; 8 MB read / 1 MB write, L2-resident.
// ---------------------------------------------------------------------------
__global__ void __launch_bounds__(256) k_merge()
{
    const int i = blockIdx.x * 256 + threadIdx.x;   // float4 idx, 65536 total
    const int row = i >> 6;                         // 64 float4 per row

    float dt = 0.f;
    #pragma unroll
    for (int sp = 0; sp < 8; ++sp) dt += g_den[sp][row];
    const float inv = 1.0f / dt;

    float4 s = make_float4(0.f, 0.f, 0.f, 0.f);
    #pragma unroll
    for (int sp = 0; sp < 8; ++sp) {
        float4 p = *(const float4*)&g_pvp[sp][(size_t)i * 4];
        s.x += p.x; s.y += p.y; s.z += p.z; s.w += p.w;
    }
    float h0 = s.x * inv, h1 = s.y * inv, h2 = s.z * inv, h3 = s.w * inv;
    float4 r;
    r.x = (h0 > 0.f) ? h0 : 0.01f * h0;
    r.y = (h1 > 0.f) ? h1 : 0.01f * h1;
    r.z = (h2 > 0.f) ? h2 : 0.01f * h2;
    r.w = (h3 > 0.f) ? h3 : 0.01f * h3;
    *(float4*)&g_heads[(size_t)i * 4] = r;
}

// ---------------------------------------------------------------------------
// K4: out = heads @ Wr^T + bias.  Plain GEMM, 64(m) x 32(n) tiles, K=256.
// 128 blocks x 256 threads, 2x4 micro-tile, packed f32x2 FMA. No partials.
// A fragments read as scalar LDS.32 (stride-65 rows are 4B-aligned only;
// this keeps the conflict-free transpose-store layout legal).
// ---------------------------------------------------------------------------
__global__ void __launch_bounds__(256) k_out(
    const float* __restrict__ Wr, const float* __restrict__ br_p,
    float* __restrict__ out)
{
    const int n = blockIdx.z;
    const int m0 = blockIdx.y * 64, n0 = blockIdx.x * 32;
    const float* A = g_heads + (size_t)n * NQ * NE;

    __shared__ float As[32][65];   // stride == 1 mod 32: conflict-free stores
    __shared__ float Bs[32][36];

    const int tid = threadIdx.x;
    const int tx = tid & 7, ty = tid >> 3;          // 8 x 32 -> 4 cols x 2 rows
    const int ar = tid >> 2, ac = (tid & 3) * 8;    // A stage: 64 rows x 32 k
    const int bj = tid >> 3, bkc = (tid & 7) * 4;   // B stage: 32 j x 32 k

    unsigned long long acc[2][2] = {};

    for (int k0 = 0; k0 < NE; k0 += 32) {
        float4 a0 = *(const float4*)&A[(size_t)(m0 + ar) * NE + k0 + ac];
        float4 a1 = *(const float4*)&A[(size_t)(m0 + ar) * NE + k0 + ac + 4];
        As[ac + 0][ar] = a0.x; As[ac + 1][ar] = a0.y;
        As[ac + 2][ar] = a0.z; As[ac + 3][ar] = a0.w;
        As[ac + 4][ar] = a1.x; As[ac + 5][ar] = a1.y;
        As[ac + 6][ar] = a1.z; As[ac + 7][ar] = a1.w;
        // Bs[k][j] = Wr[(n0+j)*NE + k0+k]
        float4 w0 = *(const float4*)&Wr[(size_t)(n0 + bj) * NE + k0 + bkc];
        Bs[bkc + 0][bj] = w0.x; Bs[bkc + 1][bj] = w0.y;
        Bs[bkc + 2][bj] = w0.z; Bs[bkc + 3][bj] = w0.w;
        __syncthreads();
        #pragma unroll
        for (int k = 0; k < 32; ++k) {
            float avx = As[k][ty * 2];       // scalar LDS: 4B-aligned, bcast
            float avy = As[k][ty * 2 + 1];
            ulonglong2 bv = *(const ulonglong2*)&Bs[k][tx * 4];
            ffma2(acc[0][0], splat2(avx), bv.x);
            ffma2(acc[0][1], splat2(avx), bv.y);
            ffma2(acc[1][0], splat2(avy), bv.x);
            ffma2(acc[1][1], splat2(avy), bv.y);
        }
        __syncthreads();
    }

    float4 b4 = *(const float4*)&br_p[n0 + tx * 4];
    #pragma unroll
    for (int i = 0; i < 2; ++i) {
        float2 lo = *reinterpret_cast<float2*>(&acc[i][0]);
        float2 hi = *reinterpret_cast<float2*>(&acc[i][1]);
        float4 r = make_float4(lo.x + b4.x, lo.y + b4.y, hi.x + b4.z, hi.y + b4.w);
        *(float4*)&out[((size_t)n * NQ + m0 + ty * 2 + i) * NE + n0 + tx * 4] = r;
    }
}

// ---------------------------------------------------------------------------
extern "C" void kernel_launch(void* const* d_in, const int* in_sizes, int n_in,
                              void* d_out, int out_size)
{
    const float* query   = (const float*)d_in[0];
    const float* context = (const float*)d_in[1];
    const float* memory  = (const float*)d_in[2];
    const float* w_logit = (const float*)d_in[3];
    const float* b_logit = (const float*)d_in[4];
    const float* temp    = (const float*)d_in[5];
    const float* w_red   = (const float*)d_in[6];
    const float* b_red   = (const float*)d_in[7];
    float* out = (float*)d_out;

    dim3 g1(NQ / 8, NV / 64, NN);        // 32 x 8 x 4 = 1024 blocks
    k_logits<<<g1, 256>>>(query, context, w_logit, b_logit);

    dim3 g2(NE / 64, NQ / 64, NN * 8);   // 4 x 4 x 32 = 512 blocks
    k_pv<<<g2, 256>>>(memory, temp);

    k_merge<<<256, 256>>>();             // 65536 float4

    dim3 g4(NE / 32, NQ / 64, NN);       // 8 x 4 x 4 = 128 blocks
    k_out<<<g4, 256>>>(w_red, b_red, out);
}